// round 2
// baseline (speedup 1.0000x reference)
#include <cuda_runtime.h>

#define NUM_CLASSES 601
#define OUT_DIM     27
#define TAB_ELEMS   (NUM_CLASSES * OUT_DIM)   // 16227 floats = 64908 bytes

// Precomputed softmax table (softmax of each of the 601 rows of W).
// __device__ global => no runtime allocation (harness alloc guards).
__device__ float g_probs[TAB_ELEMS];

// One block per class row; lane j handles column j (j < 27), warp-reduce the sum.
__global__ void build_probs_kernel(const float* __restrict__ W) {
    int r = blockIdx.x;
    int l = threadIdx.x;
    float e = 0.0f;
    if (l < OUT_DIM) e = expf(W[r * OUT_DIM + l]);
    float s = e;
    #pragma unroll
    for (int o = 16; o; o >>= 1) s += __shfl_xor_sync(0xffffffffu, s, o);
    if (l < OUT_DIM) g_probs[r * OUT_DIM + l] = e / s;
}

// Flat gather over the output, vectorized as float4.
// Each thread produces 4 consecutive flat output elements -> one STG.128.
// row = i/27 via compiler magic-multiply; idx[row] and g_probs[...] are L1-hot.
__global__ void gather_kernel(const int* __restrict__ idx,
                              float4* __restrict__ out4,
                              unsigned n4) {
    unsigned t = blockIdx.x * blockDim.x + threadIdx.x;
    if (t >= n4) return;
    unsigned base = t * 4u;
    float v[4];
    #pragma unroll
    for (int k = 0; k < 4; k++) {
        unsigned ik  = base + (unsigned)k;
        unsigned row = ik / 27u;                 // magic-multiply, no real div
        unsigned col = ik - row * 27u;
        int b = __ldg(&idx[row]);                // broadcast within warp, L1 hit
        v[k] = __ldg(&g_probs[b * OUT_DIM + col]); // 65KB table, L1-resident
    }
    float4 o;
    o.x = v[0]; o.y = v[1]; o.z = v[2]; o.w = v[3];
    out4[t] = o;
}

extern "C" void kernel_launch(void* const* d_in, const int* in_sizes, int n_in,
                              void* d_out, int out_size) {
    // Inputs in metadata order: bigram_idx (int32, BATCH), W (float32, 601*27).
    // Be robust to ordering by identifying W via its element count.
    const int*   idx = (const int*)d_in[0];
    const float* W   = (const float*)d_in[1];
    if (n_in >= 2 && in_sizes[0] == TAB_ELEMS) {
        W   = (const float*)d_in[0];
        idx = (const int*)d_in[1];
    }
    float* out = (float*)d_out;

    // 1) 601-row softmax table (tiny: 601 warps of work).
    build_probs_kernel<<<NUM_CLASSES, 32>>>(W);

    // 2) Store-bound gather: out_size = BATCH*27, divisible by 4.
    unsigned n4 = (unsigned)(out_size / 4);
    unsigned threads = 256;
    unsigned blocks  = (n4 + threads - 1) / threads;
    gather_kernel<<<blocks, threads>>>(idx, (float4*)out, n4);
}